// round 2
// baseline (speedup 1.0000x reference)
#include <cuda_runtime.h>

// 3D trilinear grid_sample, align_corners=False, padding_mode='border'
// image: [B, C, D, H, W] float32
// flow:  [B, 3, D, H, W] float32 (x,y,z displacements in voxels)
// out:   [B, C, D, H, W] float32

#define B_ 2
#define C_ 2
#define D_ 128
#define H_ 128
#define W_ 128

// Fetch image[row + x0] and image[row + x0 + 1] (x-pair) via one aligned
// float4 load, plus a predicated second load only when the pair straddles a
// 16B quad boundary. 'hi' is false when x0 == W-1 (then v1 := v0; its weight
// tx is 0 anyway).
__device__ __forceinline__ float2 fetch_pair(const float* __restrict__ row,
                                             int a /*x0 & ~3*/, int r /*x0 & 3*/,
                                             bool hi /*r==3 && x0 < W-1*/)
{
    float4 q = __ldg(reinterpret_cast<const float4*>(row + a));
    float v0, v1;
    if (r == 0)      { v0 = q.x; v1 = q.y; }
    else if (r == 1) { v0 = q.y; v1 = q.z; }
    else if (r == 2) { v0 = q.z; v1 = q.w; }
    else {
        v0 = q.w;
        v1 = q.w;                       // border case (x0 == W-1): tx == 0
        if (hi) {
            float4 q2 = __ldg(reinterpret_cast<const float4*>(row + a + 4));
            v1 = q2.x;
        }
    }
    return make_float2(v0, v1);
}

__global__ __launch_bounds__(256) void warp3d_kernel(
    const float* __restrict__ image,
    const float* __restrict__ flow,
    float* __restrict__ out)
{
    constexpr int N = D_ * H_ * W_;
    int tid = blockIdx.x * blockDim.x + threadIdx.x;
    if (tid >= B_ * N) return;

    int b = tid / N;
    int p = tid - b * N;                        // z*H*W + y*W + x
    int x = p & (W_ - 1);
    int y = (p >> 7) & (H_ - 1);
    int z = p >> 14;

    const float* fb = flow + (size_t)b * 3 * N;
    float fx = __ldg(fb + p);
    float fy = __ldg(fb + N + p);
    float fz = __ldg(fb + 2 * N + p);

    constexpr float sW = (float)W_ / (float)(W_ - 1);
    constexpr float sH = (float)H_ / (float)(H_ - 1);
    constexpr float sD = (float)D_ / (float)(D_ - 1);

    float ix = fminf(fmaxf(fmaf((float)x + fx, sW, -0.5f), 0.0f), (float)(W_ - 1));
    float iy = fminf(fmaxf(fmaf((float)y + fy, sH, -0.5f), 0.0f), (float)(H_ - 1));
    float iz = fminf(fmaxf(fmaf((float)z + fz, sD, -0.5f), 0.0f), (float)(D_ - 1));

    float x0f = floorf(ix), y0f = floorf(iy), z0f = floorf(iz);
    float tx = ix - x0f, ty = iy - y0f, tz = iz - z0f;

    int x0 = (int)x0f, y0 = (int)y0f, z0 = (int)z0f;
    int y1 = min(y0 + 1, H_ - 1);
    int z1 = min(z0 + 1, D_ - 1);

    int a = x0 & ~3;
    int r = x0 & 3;
    bool hi = (r == 3) && (x0 < W_ - 1);

    // 4 corner-row base offsets (shared by both channels)
    int zy00 = (z0 * H_ + y0) * W_;
    int zy01 = (z0 * H_ + y1) * W_;
    int zy10 = (z1 * H_ + y0) * W_;
    int zy11 = (z1 * H_ + y1) * W_;

    #pragma unroll
    for (int c = 0; c < C_; c++) {
        const float* img = image + ((size_t)b * C_ + c) * N;

        float2 p00 = fetch_pair(img + zy00, a, r, hi);
        float2 p01 = fetch_pair(img + zy01, a, r, hi);
        float2 p10 = fetch_pair(img + zy10, a, r, hi);
        float2 p11 = fetch_pair(img + zy11, a, r, hi);

        // lerp x, then y, then z
        float cx00 = fmaf(tx, p00.y - p00.x, p00.x);
        float cx01 = fmaf(tx, p01.y - p01.x, p01.x);
        float cx10 = fmaf(tx, p10.y - p10.x, p10.x);
        float cx11 = fmaf(tx, p11.y - p11.x, p11.x);

        float cy0 = fmaf(ty, cx01 - cx00, cx00);
        float cy1 = fmaf(ty, cx11 - cx10, cx10);

        out[((size_t)b * C_ + c) * N + p] = fmaf(tz, cy1 - cy0, cy0);
    }
}

extern "C" void kernel_launch(void* const* d_in, const int* in_sizes, int n_in,
                              void* d_out, int out_size)
{
    const float* image = (const float*)d_in[0];
    const float* flow  = (const float*)d_in[1];
    float* out = (float*)d_out;

    constexpr int total = B_ * D_ * H_ * W_;
    dim3 block(256);
    dim3 grid((total + 255) / 256);
    warp3d_kernel<<<grid, block>>>(image, flow, out);
}

// round 3
// speedup vs baseline: 1.5658x; 1.5658x over previous
#include <cuda_runtime.h>

// 3D trilinear grid_sample, align_corners=False, padding_mode='border'
// image: [B, C, D, H, W] float32   (B=2, C=2, D=H=W=128)
// flow:  [B, 3, D, H, W] float32
// out:   [B, C, D, H, W] float32
//
// Two-pass: (1) transpose image to channel-interleaved float2 scratch,
// (2) gather with one LDG.64 per corner (both channels at once).

#define B_ 2
#define C_ 2
#define D_ 128
#define H_ 128
#define W_ 128
#define N_ (D_ * H_ * W_)

// channel-interleaved scratch: [B][D*H*W] of (c0, c1)
__device__ float2 g_img2[B_][N_];

__global__ __launch_bounds__(256) void interleave_kernel(
    const float* __restrict__ image)
{
    // each thread handles 4 consecutive voxels of one batch
    int t = blockIdx.x * blockDim.x + threadIdx.x;   // 0 .. B*N/4-1
    int b = t / (N_ / 4);
    int p4 = (t - b * (N_ / 4)) * 4;

    const float4 c0 = __ldg(reinterpret_cast<const float4*>(
        image + ((size_t)b * C_ + 0) * N_ + p4));
    const float4 c1 = __ldg(reinterpret_cast<const float4*>(
        image + ((size_t)b * C_ + 1) * N_ + p4));

    float2* dst = &g_img2[b][p4];
    // two float4 stores (= four float2s)
    float4* d4 = reinterpret_cast<float4*>(dst);
    d4[0] = make_float4(c0.x, c1.x, c0.y, c1.y);
    d4[1] = make_float4(c0.z, c1.z, c0.w, c1.w);
}

__global__ __launch_bounds__(256) void warp3d_kernel(
    const float* __restrict__ flow,
    float* __restrict__ out)
{
    int tid = blockIdx.x * blockDim.x + threadIdx.x;
    if (tid >= B_ * N_) return;

    int b = tid / N_;
    int p = tid - b * N_;                       // z*H*W + y*W + x
    int x = p & (W_ - 1);
    int y = (p >> 7) & (H_ - 1);
    int z = p >> 14;

    const float* fb = flow + (size_t)b * 3 * N_;
    float fx = __ldg(fb + p);
    float fy = __ldg(fb + N_ + p);
    float fz = __ldg(fb + 2 * N_ + p);

    constexpr float sW = (float)W_ / (float)(W_ - 1);
    constexpr float sH = (float)H_ / (float)(H_ - 1);
    constexpr float sD = (float)D_ / (float)(D_ - 1);

    float ix = fminf(fmaxf(fmaf((float)x + fx, sW, -0.5f), 0.0f), (float)(W_ - 1));
    float iy = fminf(fmaxf(fmaf((float)y + fy, sH, -0.5f), 0.0f), (float)(H_ - 1));
    float iz = fminf(fmaxf(fmaf((float)z + fz, sD, -0.5f), 0.0f), (float)(D_ - 1));

    float x0f = floorf(ix), y0f = floorf(iy), z0f = floorf(iz);
    float tx = ix - x0f, ty = iy - y0f, tz = iz - z0f;

    int x0 = (int)x0f, y0 = (int)y0f, z0 = (int)z0f;
    int x1 = min(x0 + 1, W_ - 1);
    int y1 = min(y0 + 1, H_ - 1);
    int z1 = min(z0 + 1, D_ - 1);

    const float2* img = g_img2[b];

    int zy00 = (z0 * H_ + y0) * W_;
    int zy01 = (z0 * H_ + y1) * W_;
    int zy10 = (z1 * H_ + y0) * W_;
    int zy11 = (z1 * H_ + y1) * W_;

    // 8 corner fetches, each LDG.64 pulling both channels
    float2 v000 = __ldg(img + zy00 + x0);
    float2 v001 = __ldg(img + zy00 + x1);
    float2 v010 = __ldg(img + zy01 + x0);
    float2 v011 = __ldg(img + zy01 + x1);
    float2 v100 = __ldg(img + zy10 + x0);
    float2 v101 = __ldg(img + zy10 + x1);
    float2 v110 = __ldg(img + zy11 + x0);
    float2 v111 = __ldg(img + zy11 + x1);

    // trilinear: lerp x, then y, then z — on both channels
    float cx00x = fmaf(tx, v001.x - v000.x, v000.x);
    float cx00y = fmaf(tx, v001.y - v000.y, v000.y);
    float cx01x = fmaf(tx, v011.x - v010.x, v010.x);
    float cx01y = fmaf(tx, v011.y - v010.y, v010.y);
    float cx10x = fmaf(tx, v101.x - v100.x, v100.x);
    float cx10y = fmaf(tx, v101.y - v100.y, v100.y);
    float cx11x = fmaf(tx, v111.x - v110.x, v110.x);
    float cx11y = fmaf(tx, v111.y - v110.y, v110.y);

    float cy0x = fmaf(ty, cx01x - cx00x, cx00x);
    float cy0y = fmaf(ty, cx01y - cx00y, cx00y);
    float cy1x = fmaf(ty, cx11x - cx10x, cx10x);
    float cy1y = fmaf(ty, cx11y - cx10y, cx10y);

    out[((size_t)b * C_ + 0) * N_ + p] = fmaf(tz, cy1x - cy0x, cy0x);
    out[((size_t)b * C_ + 1) * N_ + p] = fmaf(tz, cy1y - cy0y, cy0y);
}

extern "C" void kernel_launch(void* const* d_in, const int* in_sizes, int n_in,
                              void* d_out, int out_size)
{
    const float* image = (const float*)d_in[0];
    const float* flow  = (const float*)d_in[1];
    float* out = (float*)d_out;

    {
        constexpr int total = B_ * N_ / 4;
        interleave_kernel<<<(total + 255) / 256, 256>>>(image);
    }
    {
        constexpr int total = B_ * N_;
        warp3d_kernel<<<(total + 255) / 256, 256>>>(flow, out);
    }
}